// round 6
// baseline (speedup 1.0000x reference)
#include <cuda_runtime.h>
#include <cuda_bf16.h>

// kspaceMap: out (32,129,128,128) f32.
//   ch 0..127: sep[b,w,h,w'] = (Re(t)cos(2pi w w'/128) - Im(t)sin(..))/128,
//              t = row DFT_128 of input[:,0]. sep[128-w] == sep[w] (real input).
//   ch 128:    copy of input[b,1,:,:].  mask unused.
//
// R6: prepass transposes ch0 into xT4[b][u4][h] (2MB, L2-resident). Fused main
// kernel CTA=(w 0..64, b): DFT bin w for all 128 rows read COALESCED from xT4
// with a warp-uniform permuted twiddle table (zero rotation FMAs), then the
// proven contiguous slab store (STG.128 .cs + mirror channel). smem 4KB, occ 8.

#define IM  128
#define BZ  32
#define CH_OUT 129

typedef unsigned long long u64;

__device__ float4 g_xT4[BZ * 32 * IM];   // [b][u4][h] : float4 = x[4u4..4u4+3][h]

static __device__ __forceinline__ u64 f2x(float a, float b) {
    u64 r; asm("mov.b64 %0, {%1, %2};" : "=l"(r) : "f"(a), "f"(b)); return r;
}
static __device__ __forceinline__ u64 mul2(u64 a, u64 b) {
    u64 d; asm("mul.rn.f32x2 %0, %1, %2;" : "=l"(d) : "l"(a), "l"(b)); return d;
}
static __device__ __forceinline__ u64 fma2(u64 a, u64 b, u64 c) {
    u64 d; asm("fma.rn.f32x2 %0, %1, %2, %3;" : "=l"(d) : "l"(a), "l"(b), "l"(c)); return d;
}
static __device__ __forceinline__ float2 unpk(u64 v) {
    float2 r; asm("mov.b64 {%0, %1}, %2;" : "=f"(r.x), "=f"(r.y) : "l"(v)); return r;
}

// ---- Prepass: per-image transpose of channel 0 into g_xT4 ----
__global__ void __launch_bounds__(256) transpose_kernel(const float* __restrict__ in)
{
    const int b   = blockIdx.x;
    const int tid = threadIdx.x;
    __shared__ float xs[64 * 129];       // half-image tile, stride-129 pad
    const unsigned in0 = ((unsigned)b) << 15;

    #pragma unroll 1
    for (int p = 0; p < 2; ++p) {
        if (p) __syncthreads();
        const unsigned src = in0 + (unsigned)p * 8192u;
        #pragma unroll 8
        for (int j = 0; j < 32; ++j) {   // coalesced LDG -> padded STS (CF)
            const int e = j * 256 + tid;
            xs[(e >> 7) * 129 + (e & 127)] = in[src + (unsigned)e];
        }
        __syncthreads();
        #pragma unroll 8
        for (int j = 0; j < 8; ++j) {    // gather (CF, stride-129) -> coalesced STG.128
            const int o  = j * 256 + tid;       // 0..2047
            const int u4 = o >> 6;
            const int hl = o & 63;
            const float* r = xs + hl * 129 + 4 * u4;
            g_xT4[((unsigned)b * 32 + u4) * IM + 64 * p + hl] =
                make_float4(r[0], r[1], r[2], r[3]);
        }
    }
}

// ---- Main: CTA (w,b) computes bin w for all rows, writes channel + mirror ----
__global__ void __launch_bounds__(256) kspace_main(const float* __restrict__ in,
                                                   float* __restrict__ out)
{
    const int w   = blockIdx.x;          // 0..64
    const int b   = blockIdx.y;          // 0..31
    const int tid = threadIdx.x;

    __shared__ __align__(16) float2 tperm[IM];  // e(u*w mod 128), warp-uniform reads
    __shared__ float  pre[256], pim[256];
    __shared__ float2 tws[IM];                  // t[b,h,w]/128

    if (tid < IM) {
        const int m = (tid * w) & (IM - 1);
        float s, c;  sincospif((float)m * (1.0f / 64.0f), &s, &c);
        tperm[tid] = make_float2(c, s);
    }

    // store-stage twiddles: thread owns w' = (tid&31)*4 + k
    float sc[4], sn[4];
    #pragma unroll
    for (int k = 0; k < 4; ++k) {
        const int m = (w * ((tid & 31) * 4 + k)) & (IM - 1);
        sincospif((float)m * (1.0f / 64.0f), &sn[k], &sc[k]);
    }
    const u64 C01 = f2x(sc[0], sc[1]), S01 = f2x(sn[0], sn[1]);
    const u64 C23 = f2x(sc[2], sc[3]), S23 = f2x(sn[2], sn[3]);
    __syncthreads();

    // DFT: thread = (row h = tid&127, u-half = tid>>7), 64 u each.
    {
        const int h  = tid & (IM - 1);
        const int uh = tid >> 7;
        float re = 0.0f, im = 0.0f;
        const float4* xp = g_xT4 + (((unsigned)b * 32 + (unsigned)uh * 16) * IM + h);
        const float4* tp = (const float4*)(tperm + uh * 64);
        #pragma unroll
        for (int j = 0; j < 16; ++j) {
            const float4 xv = xp[(unsigned)j * IM];   // coalesced, L2-hot
            const float4 t0 = tp[2 * j];              // (c,s) u, u+1 — LDS broadcast
            const float4 t1 = tp[2 * j + 1];          // (c,s) u+2, u+3
            re = fmaf(xv.x, t0.x, re);  im = fmaf(xv.x, -t0.y, im);
            re = fmaf(xv.y, t0.z, re);  im = fmaf(xv.y, -t0.w, im);
            re = fmaf(xv.z, t1.x, re);  im = fmaf(xv.z, -t1.y, im);
            re = fmaf(xv.w, t1.z, re);  im = fmaf(xv.w, -t1.w, im);
        }
        pre[tid] = re;  pim[tid] = im;
    }
    __syncthreads();
    if (tid < IM) {
        tws[tid] = make_float2((pre[tid] + pre[tid + 128]) * (1.0f / IM),
                               (pim[tid] + pim[tid + 128]) * (1.0f / IM));
    }
    __syncthreads();

    // Contiguous slab stores (R4-proven): direct + mirror channel; w==64 copies ch128.
    const unsigned chA = ((unsigned)(b * CH_OUT + w))        << 14;
    const unsigned chM = ((unsigned)(b * CH_OUT + (IM - w))) << 14;
    const unsigned chC = ((unsigned)(b * CH_OUT + IM))       << 14;
    const unsigned in1 = (((unsigned)b) << 15) + (1u << 14);
    const bool dm     = (w >= 1) && (w <= 63);
    const bool docopy = (w == 64);
    const unsigned poff = (unsigned)tid * 4u;

    #pragma unroll
    for (int it = 0; it < 16; ++it) {
        const float2 tt = tws[it * 8 + (tid >> 5)];   // LDS broadcast
        const u64 trx = f2x(tt.x, tt.x);
        const float nti = -tt.y;
        const u64 ntx = f2x(nti, nti);
        const u64 v01 = fma2(ntx, S01, mul2(trx, C01));
        const u64 v23 = fma2(ntx, S23, mul2(trx, C23));
        const float2 a = unpk(v01), d = unpk(v23);
        const float4 vv = make_float4(a.x, a.y, d.x, d.y);
        const unsigned off = poff + (unsigned)it * 1024u;
        __stcs((float4*)(out + chA + off), vv);
        if (dm) __stcs((float4*)(out + chM + off), vv);
        if (docopy) {
            const float4 cp = __ldcs((const float4*)(in + in1 + off));
            __stcs((float4*)(out + chC + off), cp);
        }
    }
}

extern "C" void kernel_launch(void* const* d_in, const int* in_sizes, int n_in,
                              void* d_out, int out_size)
{
    const float* in  = (const float*)d_in[0];   // (32,2,128,128) f32
    float*       out = (float*)d_out;           // (32,129,128,128) f32
    (void)in_sizes; (void)n_in; (void)out_size;

    transpose_kernel<<<BZ, 256>>>(in);
    kspace_main<<<dim3(65, BZ), 256>>>(in, out);
}

// round 7
// speedup vs baseline: 1.0371x; 1.0371x over previous
#include <cuda_runtime.h>
#include <cuda_bf16.h>

// kspaceMap: out (32,129,128,128) f32.
//   ch 0..127: sep[b,w,h,w'] = (Re(t)cos(2pi w w'/128) - Im(t)sin(..))/128,
//              t = row DFT_128 of input[:,0]. sep[128-w] == sep[w] (real input).
//   ch 128:    copy of input[b,1,:,:].  mask unused.
//
// R7: ONE kernel. bids 0..255 = producers (b,hg): folded table-DFT of 16 rows
// -> g_t[b][w][h], then flag[b]++. bids 256..1295 = consumers: 2 slab units
// each ((b,w) -> contiguous 64KB channel + mirror, STG.128 .cs), spin on
// flag[b]==8 with nanosleep. done[b] counter resets flags for graph replays.

#define IM  128
#define BZ  32
#define CH_OUT 129
#define NPROD 256
#define NCONS 1040

typedef unsigned long long u64;

__device__ float2 g_t[BZ * 65 * IM];   // [b][w][h], t/128
__device__ int    g_flag[BZ];
__device__ int    g_done[BZ];

static __device__ __forceinline__ u64 f2x(float a, float b) {
    u64 r; asm("mov.b64 %0, {%1, %2};" : "=l"(r) : "f"(a), "f"(b)); return r;
}
static __device__ __forceinline__ u64 mul2(u64 a, u64 b) {
    u64 d; asm("mul.rn.f32x2 %0, %1, %2;" : "=l"(d) : "l"(a), "l"(b)); return d;
}
static __device__ __forceinline__ u64 fma2(u64 a, u64 b, u64 c) {
    u64 d; asm("fma.rn.f32x2 %0, %1, %2, %3;" : "=l"(d) : "l"(a), "l"(b), "l"(c)); return d;
}
static __device__ __forceinline__ float2 unpk(u64 v) {
    float2 r; asm("mov.b64 {%0, %1}, %2;" : "=f"(r.x), "=f"(r.y) : "l"(v)); return r;
}

__global__ void __launch_bounds__(256) kspace_pc(const float* __restrict__ in,
                                                 float* __restrict__ out)
{
    const int bid = blockIdx.x;
    const int tid = threadIdx.x;
    const int wj   = tid >> 5;        // warp id 0..7
    const int lane = tid & 31;

    __shared__ float  xs[16 * 132];   // 16 input rows, pad 132 (16B-aligned, CF)
    __shared__ float  ypS[16 * 68];   // x_u + x_{u+64}, pad 68
    __shared__ float  ymS[16 * 68];   // x_u - x_{u+64}
    __shared__ float4 tab4[8][32];    // per-warp 64 x float2 twiddle table
    __shared__ float2 st[IM];         // consumer: t slice

    if (bid < NPROD) {
        // ================= PRODUCER: (b, hg) -> g_t[b][*][hg*16..+15] ========
        const int b  = bid >> 3;
        const int hg = bid & 7;

        // stage 16 rows of input[b,0], coalesced
        #pragma unroll
        for (int j = 0; j < 8; ++j) {
            const int e = j * 256 + tid;          // 0..2047
            const int row = e >> 7, col = e & 127;
            xs[row * 132 + col] = in[((unsigned)b << 15) + ((unsigned)(hg * 16 + row) << 7) + col];
        }
        __syncthreads();

        // u-fold: y+/- over u<64
        #pragma unroll
        for (int j = 0; j < 4; ++j) {
            const int e = j * 256 + tid;          // 0..1023
            const int row = e >> 6, u = e & 63;
            const float a = xs[row * 132 + u];
            const float d = xs[row * 132 + u + 64];
            ypS[row * 68 + u] = a + d;
            ymS[row * 68 + u] = a - d;
        }
        __syncthreads();

        // per-warp bins: w = wj, wj+8, ... <= 64
        const int row = lane & 15;
        const int uh  = lane >> 4;
        for (int w = wj; w <= 64; w += 8) {
            // build 64-entry table e((u*w)&127): lane fills u = 2*lane, 2*lane+1
            __syncwarp();
            {
                float2* tabw = (float2*)&tab4[wj][0];
                #pragma unroll
                for (int k = 0; k < 2; ++k) {
                    const int u = 2 * lane + k;
                    const int m = (u * w) & (IM - 1);
                    float s, c;  sincospif((float)m * (1.0f / 64.0f), &s, &c);
                    tabw[u] = make_float2(c, s);
                }
            }
            __syncwarp();

            const float* yb = (w & 1) ? ymS : ypS;
            const float4* Y = (const float4*)(yb + row * 68 + uh * 32);
            const float4* T = &tab4[wj][uh * 16];
            float re = 0.0f, im = 0.0f;
            #pragma unroll
            for (int i = 0; i < 8; ++i) {
                const float4 y4 = Y[i];
                const float4 t0 = T[2 * i], t1 = T[2 * i + 1];
                re = fmaf(y4.x, t0.x, re);  im = fmaf(y4.x, -t0.y, im);
                re = fmaf(y4.y, t0.z, re);  im = fmaf(y4.y, -t0.w, im);
                re = fmaf(y4.z, t1.x, re);  im = fmaf(y4.z, -t1.y, im);
                re = fmaf(y4.w, t1.z, re);  im = fmaf(y4.w, -t1.w, im);
            }
            re += __shfl_xor_sync(0xffffffffu, re, 16);
            im += __shfl_xor_sync(0xffffffffu, im, 16);
            if (lane < 16)
                g_t[((unsigned)b * 65 + w) * IM + hg * 16 + row] =
                    make_float2(re * (1.0f / IM), im * (1.0f / IM));
        }

        __syncthreads();
        if (tid == 0) {
            __threadfence();
            atomicAdd(&g_flag[b], 1);
        }
        return;
    }

    // ================= CONSUMER: 2 slab units =================
    const int c = bid - NPROD;                   // 0..1039
    #pragma unroll 1
    for (int half = 0; half < 2; ++half) {
        const int u = c + half * NCONS;          // 0..2079
        const int b = u & 31;
        const int w = u >> 5;                    // 0..64

        if (tid == 0) {
            while (*(volatile int*)&g_flag[b] < 8) __nanosleep(128);
            __threadfence();
        }
        __syncthreads();

        if (tid < IM) st[tid] = g_t[((unsigned)b * 65 + w) * IM + tid];

        // per-thread store twiddles: w' = (tid&31)*4 + k
        float sc[4], sn[4];
        #pragma unroll
        for (int k = 0; k < 4; ++k) {
            const int m = (w * ((tid & 31) * 4 + k)) & (IM - 1);
            sincospif((float)m * (1.0f / 64.0f), &sn[k], &sc[k]);
        }
        const u64 C01 = f2x(sc[0], sc[1]), S01 = f2x(sn[0], sn[1]);
        const u64 C23 = f2x(sc[2], sc[3]), S23 = f2x(sn[2], sn[3]);
        __syncthreads();

        const unsigned chA = ((unsigned)(b * CH_OUT + w))        << 14;
        const unsigned chM = ((unsigned)(b * CH_OUT + (IM - w))) << 14;
        const unsigned chC = ((unsigned)(b * CH_OUT + IM))       << 14;
        const unsigned in1 = (((unsigned)b) << 15) + (1u << 14);
        const bool dm     = (w >= 1) && (w <= 63);
        const bool docopy = (w == 64);
        const unsigned poff = (unsigned)tid * 4u;

        #pragma unroll
        for (int it = 0; it < 16; ++it) {
            const float2 tt = st[it * 8 + (tid >> 5)];    // LDS broadcast
            const u64 trx = f2x(tt.x, tt.x);
            const float nti = -tt.y;
            const u64 ntx = f2x(nti, nti);
            const u64 v01 = fma2(ntx, S01, mul2(trx, C01));
            const u64 v23 = fma2(ntx, S23, mul2(trx, C23));
            const float2 a = unpk(v01), d = unpk(v23);
            const float4 vv = make_float4(a.x, a.y, d.x, d.y);
            const unsigned off = poff + (unsigned)it * 1024u;
            __stcs((float4*)(out + chA + off), vv);
            if (dm) __stcs((float4*)(out + chM + off), vv);
            if (docopy) {
                const float4 cp = __ldcs((const float4*)(in + in1 + off));
                __stcs((float4*)(out + chC + off), cp);
            }
        }

        __syncthreads();     // st reuse guard before next half
        if (tid == 0) {
            const int v = atomicAdd(&g_done[b], 1);
            if (v == 64) {                       // last of 65 units for this b
                g_flag[b] = 0;
                __threadfence();
                g_done[b] = 0;                   // reset for next graph replay
            }
        }
    }
}

extern "C" void kernel_launch(void* const* d_in, const int* in_sizes, int n_in,
                              void* d_out, int out_size)
{
    const float* in  = (const float*)d_in[0];   // (32,2,128,128) f32
    float*       out = (float*)d_out;           // (32,129,128,128) f32
    (void)in_sizes; (void)n_in; (void)out_size;

    kspace_pc<<<NPROD + NCONS, 256>>>(in, out);
}

// round 8
// speedup vs baseline: 1.3464x; 1.2982x over previous
#include <cuda_runtime.h>
#include <cuda_bf16.h>

// kspaceMap: out (32,129,128,128) f32.
//   ch 0..127: sep[b,w,h,w'] = (Re(t)cos(2pi w w'/128) - Im(t)sin(..))/128,
//              t = row DFT_128 of input[:,0]. sep[128-w] == sep[w] (real input).
//   ch 128:    copy of input[b,1,:,:].  mask unused.
//
// R8 = R3 refined: 256 threads per (b,h) row.
//  - u-fold (y+/-) halves DFT MACs; 130 DFT items x 32 MACs on warps 0-4.
//  - warp 5 does the ch128 row copy concurrently with the DFT.
//  - store stage over 8 warps (w = warp mod 8): 8-9 iters/thread, .cs hints.

#define IM  128
#define BZ  32
#define CH_OUT 129

typedef unsigned long long u64;

static __device__ __forceinline__ u64 f2x(float a, float b) {
    u64 r; asm("mov.b64 %0, {%1, %2};" : "=l"(r) : "f"(a), "f"(b)); return r;
}
static __device__ __forceinline__ u64 mul2(u64 a, u64 b) {
    u64 d; asm("mul.rn.f32x2 %0, %1, %2;" : "=l"(d) : "l"(a), "l"(b)); return d;
}
static __device__ __forceinline__ u64 fma2(u64 a, u64 b, u64 c) {
    u64 d; asm("fma.rn.f32x2 %0, %1, %2, %3;" : "=l"(d) : "l"(a), "l"(b), "l"(c)); return d;
}
static __device__ __forceinline__ float2 unpk(u64 v) {
    float2 r; asm("mov.b64 {%0, %1}, %2;" : "=f"(r.x), "=f"(r.y) : "l"(v)); return r;
}

__global__ void __launch_bounds__(256) kspace_kernel(const float* __restrict__ in,
                                                     float* __restrict__ out)
{
    const int bh  = blockIdx.x;
    const int b   = bh >> 7;
    const int h   = bh & (IM - 1);
    const int tid = threadIdx.x;
    const int wj  = tid >> 5;
    const int lane = tid & 31;

    __shared__ float  xs[IM];
    __shared__ float  yy[130];           // [parity(65-stride)][u]: y+ at 0, y- at 65
    __shared__ float  pre[130], pim[130];
    __shared__ float2 tws[65];

    // stage x row (ch0)
    if (tid < IM) xs[tid] = in[(((unsigned)b * 2) * IM + h) * IM + tid];
    __syncthreads();

    // u-fold
    if (tid < 64) {
        const float a = xs[tid], d = xs[tid + 64];
        yy[tid]      = a + d;            // even bins
        yy[65 + tid] = a - d;            // odd bins
    }
    __syncthreads();

    // ---- DFT (warps 0..4): item i = tid < 130: bin w = i%65, u-half hf = i/65.
    //      t_w = sum_{u<64} y^{(w&1)}[u] e(-2pi u w/128); 32 u per item.
    if (tid < 130) {
        const int w  = (tid < 65) ? tid : tid - 65;
        const int hf = (tid < 65) ? 0 : 1;
        float SS, SC;  sincospif((float)w * (1.0f / 64.0f), &SS, &SC);   // step
        float s, c;    sincospif((float)(hf * w) * 0.5f, &s, &c);        // u0 = 32*hf (exact)
        const float* yp = yy + (w & 1) * 65 + hf * 32;
        float re = 0.0f, im = 0.0f;
        #pragma unroll 8
        for (int i = 0; i < 32; ++i) {
            const float yv = yp[i];
            re = fmaf(yv,  c, re);
            im = fmaf(yv, -s, im);
            const float cn = fmaf(c, SC, -(s * SS));
            s = fmaf(s, SC, c * SS);
            c = cn;
        }
        pre[tid] = re;  pim[tid] = im;
    }
    // ---- concurrent ch128 row copy (warp 5): 32 lanes x float4 = 512B
    if (wj == 5) {
        const unsigned o = ((((unsigned)b * 2 + 1) * IM + h) * IM) + 4u * lane;
        const float4 cp = __ldcs((const float4*)(in + o));
        __stcs((float4*)(out + ((((unsigned)b * CH_OUT + IM) * IM + h) * IM) + 4u * lane), cp);
    }
    __syncthreads();
    if (tid < 65) {
        tws[tid] = make_float2((pre[tid] + pre[tid + 65]) * (1.0f / IM),
                               (pim[tid] + pim[tid + 65]) * (1.0f / IM));
    }
    __syncthreads();

    // ---- Store: warp j handles w = j, j+8, ... <= 64; lane owns w' = 4l..4l+3.
    //      value -> channel w and mirror channel 128-w.
    {
        float c0[4], s0[4], sc[4], ss[4];
        #pragma unroll
        for (int k = 0; k < 4; ++k) {
            const int wp = 4 * lane + k;
            const int m0 = (wj * wp) & (IM - 1);     // start angle (w = wj)
            const int ms = (8  * wp) & (IM - 1);     // step (dw = 8)
            sincospif((float)m0 * (1.0f / 64.0f), &s0[k], &c0[k]);
            sincospif((float)ms * (1.0f / 64.0f), &ss[k], &sc[k]);
        }
        u64 C01 = f2x(c0[0], c0[1]), S01 = f2x(s0[0], s0[1]);
        u64 C23 = f2x(c0[2], c0[3]), S23 = f2x(s0[2], s0[3]);
        const u64 SC01 = f2x(sc[0], sc[1]),  SS01 = f2x(ss[0], ss[1]);
        const u64 SC23 = f2x(sc[2], sc[3]),  SS23 = f2x(ss[2], ss[3]);
        const u64 NS01 = f2x(-ss[0], -ss[1]), NS23 = f2x(-ss[2], -ss[3]);

        float* p  = out + (((((unsigned)b * CH_OUT) + wj) * IM + h) * IM + 4u * lane);
        float* pm = out + (((((unsigned)b * CH_OUT) + (IM - wj)) * IM + h) * IM + 4u * lane);
        const unsigned step = 8u * IM * IM;          // 8 channels

        for (int w = wj; w <= 64; w += 8) {
            const float2 tt = tws[w];                // LDS broadcast (warp-uniform)
            const u64 trx = f2x(tt.x, tt.x);
            const float nti = -tt.y;
            const u64 ntx = f2x(nti, nti);
            const u64 v01 = fma2(ntx, S01, mul2(trx, C01));
            const u64 v23 = fma2(ntx, S23, mul2(trx, C23));
            const float2 a = unpk(v01), d = unpk(v23);
            const float4 vv = make_float4(a.x, a.y, d.x, d.y);
            __stcs((float4*)p, vv);
            if (w >= 1 && w <= 63) __stcs((float4*)pm, vv);   // warp-uniform
            p  += step;
            pm -= step;
            const u64 nC01 = fma2(S01, NS01, mul2(C01, SC01));
            S01 = fma2(C01, SS01, mul2(S01, SC01));
            C01 = nC01;
            const u64 nC23 = fma2(S23, NS23, mul2(C23, SC23));
            S23 = fma2(C23, SS23, mul2(S23, SC23));
            C23 = nC23;
        }
    }
}

extern "C" void kernel_launch(void* const* d_in, const int* in_sizes, int n_in,
                              void* d_out, int out_size)
{
    const float* in  = (const float*)d_in[0];   // (32,2,128,128) f32
    float*       out = (float*)d_out;           // (32,129,128,128) f32
    (void)in_sizes; (void)n_in; (void)out_size;

    kspace_kernel<<<BZ * IM, 256>>>(in, out);
}

// round 9
// speedup vs baseline: 1.3539x; 1.0056x over previous
#include <cuda_runtime.h>
#include <cuda_bf16.h>

// kspaceMap: out (32,129,128,128) f32.
//   ch 0..127: sep[b,w,h,w'] = (Re(t)cos(2pi w w'/128) - Im(t)sin(..))/128,
//              t = row DFT_128 of input[:,0].
//   ch 128:    copy of input[b,1,:,:].  mask unused.
// Symmetries used: sep[128-w] == sep[w] (real input); value(w,w'+64) = (-1)^w value(w,w').
//
// R9 = R8 + quarter-wave w' symmetry + paired-w half-warps + immediate-offset
// unrolled stores: ~22 issue slots per 128B stored (was ~56).

#define IM  128
#define BZ  32
#define CH_OUT 129

typedef unsigned long long u64;

static __device__ __forceinline__ u64 f2x(float a, float b) {
    u64 r; asm("mov.b64 %0, {%1, %2};" : "=l"(r) : "f"(a), "f"(b)); return r;
}
static __device__ __forceinline__ u64 mul2(u64 a, u64 b) {
    u64 d; asm("mul.rn.f32x2 %0, %1, %2;" : "=l"(d) : "l"(a), "l"(b)); return d;
}
static __device__ __forceinline__ u64 fma2(u64 a, u64 b, u64 c) {
    u64 d; asm("fma.rn.f32x2 %0, %1, %2, %3;" : "=l"(d) : "l"(a), "l"(b), "l"(c)); return d;
}
static __device__ __forceinline__ float2 unpk(u64 v) {
    float2 r; asm("mov.b64 {%0, %1}, %2;" : "=f"(r.x), "=f"(r.y) : "l"(v)); return r;
}

__global__ void __launch_bounds__(256) kspace_kernel(const float* __restrict__ in,
                                                     float* __restrict__ out)
{
    const int bh   = blockIdx.x;
    const int b    = bh >> 7;
    const int h    = bh & (IM - 1);
    const int tid  = threadIdx.x;
    const int wj   = tid >> 5;
    const int lane = tid & 31;

    __shared__ float  xs[IM];
    __shared__ float  yy[130];           // y+ at [0..63], y- at [65..128]
    __shared__ float  pre[130], pim[130];
    __shared__ float2 tws[65];

    if (tid < IM) xs[tid] = in[(((unsigned)b * 2) * IM + h) * IM + tid];
    __syncthreads();

    if (tid < 64) {
        const float a = xs[tid], d = xs[tid + 64];
        yy[tid]      = a + d;
        yy[65 + tid] = a - d;
    }
    __syncthreads();

    // ---- DFT (warps 0..4): item = (bin w, u-half hf), 32 folded MACs each ----
    if (tid < 130) {
        const int w  = (tid < 65) ? tid : tid - 65;
        const int hf = (tid < 65) ? 0 : 1;
        float SS, SC;  sincospif((float)w * (1.0f / 64.0f), &SS, &SC);
        float s, c;    sincospif((float)(hf * w) * 0.5f, &s, &c);       // u0 = 32*hf
        const float* yp = yy + (w & 1) * 65 + hf * 32;
        float re = 0.0f, im = 0.0f;
        #pragma unroll 8
        for (int i = 0; i < 32; ++i) {
            const float yv = yp[i];
            re = fmaf(yv,  c, re);
            im = fmaf(yv, -s, im);
            const float cn = fmaf(c, SC, -(s * SS));
            s = fmaf(s, SC, c * SS);
            c = cn;
        }
        pre[tid] = re;  pim[tid] = im;
    }
    // concurrent ch128 row copy (warp 5)
    if (wj == 5) {
        const unsigned o = ((((unsigned)b * 2 + 1) * IM + h) * IM) + 4u * lane;
        const float4 cp = __ldcs((const float4*)(in + o));
        __stcs((float4*)(out + ((((unsigned)b * CH_OUT + IM) * IM + h) * IM) + 4u * lane), cp);
    }
    __syncthreads();
    if (tid < 65) {
        tws[tid] = make_float2((pre[tid] + pre[tid + 65]) * (1.0f / IM),
                               (pim[tid] + pim[tid + 65]) * (1.0f / IM));
    }
    __syncthreads();

    // ---- Store stage ----
    // half-warp owns bin chain wstart = wj + 8*half, stepping 16; lane slot l16
    // owns w' = 4*l16..4*l16+3 (lo) and +64 (hi = (-1)^w * lo).
    {
        const int half = lane >> 4;
        const int l16  = lane & 15;
        const int wstart = wj + 8 * half;         // 0..15

        float c0[4], s0[4], sc[4], ss[4];
        #pragma unroll
        for (int k = 0; k < 4; ++k) {
            const int wp = 4 * l16 + k;
            sincospif((float)((wstart * wp) & 127) * (1.0f / 64.0f), &s0[k], &c0[k]);
            sincospif((float)((16 * wp) & 127) * (1.0f / 64.0f), &ss[k], &sc[k]);
        }
        u64 C01 = f2x(c0[0], c0[1]), S01 = f2x(s0[0], s0[1]);
        u64 C23 = f2x(c0[2], c0[3]), S23 = f2x(s0[2], s0[3]);
        const u64 SC01 = f2x(sc[0], sc[1]),  SS01 = f2x(ss[0], ss[1]);
        const u64 SC23 = f2x(sc[2], sc[3]),  SS23 = f2x(ss[2], ss[3]);
        const u64 NS01 = f2x(-ss[0], -ss[1]), NS23 = f2x(-ss[2], -ss[3]);
        const u64 sgn  = (wstart & 1) ? 0x8000000080000000ull : 0ull;  // (-1)^w, w parity fixed

        float* pA = out + (((unsigned)(b * CH_OUT + wstart))            << 14)
                        + ((unsigned)h << 7) + 4u * l16;
        float* pM = out + (((unsigned)(b * CH_OUT + (IM - wstart)))     << 14)
                        + ((unsigned)h << 7) + 4u * l16;
        const bool m0skip = (wstart == 0);        // w==0 mirror is ch128 (copy) — skip

        #pragma unroll
        for (int s = 0; s < 4; ++s) {
            const int w = wstart + 16 * s;        // <= 63
            const float2 tt = tws[w];             // 2 broadcasts per LDS
            const u64 trx = f2x(tt.x, tt.x);
            const float nti = -tt.y;
            const u64 ntx = f2x(nti, nti);
            const u64 v01 = fma2(ntx, S01, mul2(trx, C01));
            const u64 v23 = fma2(ntx, S23, mul2(trx, C23));
            const u64 h01 = v01 ^ sgn, h23 = v23 ^ sgn;
            const float2 a = unpk(v01), d = unpk(v23);
            const float2 ah = unpk(h01), dh = unpk(h23);
            const float4 vlo = make_float4(a.x, a.y, d.x, d.y);
            const float4 vhi = make_float4(ah.x, ah.y, dh.x, dh.y);
            __stcs((float4*)(pA + (unsigned)s * 262144u), vlo);
            __stcs((float4*)(pA + (unsigned)s * 262144u + 64u), vhi);
            if (s || !m0skip) {
                __stcs((float4*)(pM - (unsigned)s * 262144u), vlo);
                __stcs((float4*)(pM - (unsigned)s * 262144u + 64u), vhi);
            }
            const u64 nC01 = fma2(S01, NS01, mul2(C01, SC01));
            S01 = fma2(C01, SS01, mul2(S01, SC01));
            C01 = nC01;
            const u64 nC23 = fma2(S23, NS23, mul2(C23, SC23));
            S23 = fma2(C23, SS23, mul2(S23, SC23));
            C23 = nC23;
        }

        // w = 64 (warp 0, half 0 chain after 4 rotations); mirror(64)==64, store once.
        if (wj == 0 && half == 0) {
            const float2 tt = tws[64];
            const u64 trx = f2x(tt.x, tt.x);
            const float nti = -tt.y;
            const u64 ntx = f2x(nti, nti);
            const u64 v01 = fma2(ntx, S01, mul2(trx, C01));
            const u64 v23 = fma2(ntx, S23, mul2(trx, C23));
            const u64 h01 = v01 ^ sgn, h23 = v23 ^ sgn;
            const float2 a = unpk(v01), d = unpk(v23);
            const float2 ah = unpk(h01), dh = unpk(h23);
            __stcs((float4*)(pA + 4u * 262144u),       make_float4(a.x, a.y, d.x, d.y));
            __stcs((float4*)(pA + 4u * 262144u + 64u), make_float4(ah.x, ah.y, dh.x, dh.y));
        }
    }
}

extern "C" void kernel_launch(void* const* d_in, const int* in_sizes, int n_in,
                              void* d_out, int out_size)
{
    const float* in  = (const float*)d_in[0];   // (32,2,128,128) f32
    float*       out = (float*)d_out;           // (32,129,128,128) f32
    (void)in_sizes; (void)n_in; (void)out_size;

    kspace_kernel<<<BZ * IM, 256>>>(in, out);
}